// round 14
// baseline (speedup 1.0000x reference)
#include <cuda_runtime.h>

#define NB   16
#define NC   512
#define HN   4608      // H*W = 96*48
#define SEC  32        // SE bottleneck
#define NTILE 9        // HN / (128 threads * 4 floats)
#define CCH  8         // C chunks in k_proj
#define CPB  (NC/CCH)  // 64 channels per proj block
#define OCH  16        // C chunks in k_out
#define OCPB (NC/OCH)  // 32 channels per out block
#define CTILE 36       // comb: HN/128 n-tiles per batch
#define BN_EPS 1e-5f

// ---- scratch (device globals; no allocations allowed) ----
__device__ float d_xp[NB * NC];          // channel means
__device__ float d_wt[NB * NC];          // gate * theta_w
__device__ float d_wp[NB * NC];          // gate * phi_w
__device__ float d_wg[NB * NC];          // gate * g_w
__device__ float d_thp[CCH * NB * HN];   // theta partials per C-chunk
__device__ float d_php[CCH * NB * HN];   // phi partials
__device__ float d_ggp[CCH * NB * HN];   // g partials
__device__ float d_spart[NB * CTILE];    // per-(b,128n-tile) partial of sum(phi*g)
__device__ float d_coefA[NC];            // W_w * gamma/sqrt(var+eps)
__device__ float d_coefB[NC];            // (W_b-mean)*inv + beta

// ============================================================
// K1: per-(b,c) spatial mean. Warp-per-row: grid = NB*NC/8,
// block = 256 (8 warps). FORWARD order; default cache policy so
// the tail of x stays L2-resident for k_proj (which reads reversed).
// ============================================================
__global__ void k_pool(const float* __restrict__ x) {
    const int warp = threadIdx.x >> 5, lane = threadIdx.x & 31;
    const int row  = blockIdx.x * 8 + warp;          // b*NC + c
    const float4* xr = (const float4*)(x + (size_t)row * HN);
    float s = 0.f;
#pragma unroll
    for (int i = 0; i < 36; i++) {                   // HN/4/32 = 36
        float4 v = xr[lane + i * 32];
        s += (v.x + v.y) + (v.z + v.w);
    }
#pragma unroll
    for (int off = 16; off; off >>= 1) s += __shfl_xor_sync(0xffffffffu, s, off);
    if (lane == 0) d_xp[row] = s * (1.0f / HN);
}

// ============================================================
// K2: full SE MLP + fused weights + BN coefs, one kernel.
// grid = NB, block = 512.
// ============================================================
__global__ void k_se(const float* __restrict__ se_w1,
                     const float* __restrict__ se_b1,
                     const float* __restrict__ se_w2,
                     const float* __restrict__ se_b2,
                     const float* __restrict__ g_w,
                     const float* __restrict__ theta_w,
                     const float* __restrict__ phi_w,
                     const float* __restrict__ W_w,
                     const float* __restrict__ W_b,
                     const float* __restrict__ bn_gamma,
                     const float* __restrict__ bn_beta,
                     const float* __restrict__ bn_mean,
                     const float* __restrict__ bn_var) {
    const int b    = blockIdx.x;
    const int c    = threadIdx.x;
    const int lane = c & 31, warp = c >> 5;          // 16 warps
    __shared__ float sh[SEC];

    // stage 1: hid = relu(xp @ W1^T + b1); 16 warps x 2 outputs each
#pragma unroll
    for (int j = warp; j < SEC; j += 16) {
        float acc = 0.f;
#pragma unroll
        for (int k = 0; k < 16; k++) {
            const int cc = k * 32 + lane;
            acc += d_xp[b * NC + cc] * se_w1[j * NC + cc];
        }
#pragma unroll
        for (int off = 16; off; off >>= 1) acc += __shfl_xor_sync(0xffffffffu, acc, off);
        if (lane == 0) sh[j] = fmaxf(acc + se_b1[j], 0.f);
    }
    __syncthreads();

    // stage 2: gate = sigmoid(hid @ W2^T + b2), fused per-channel weights
    const float4* w2 = (const float4*)(se_w2 + c * SEC);
    float acc = se_b2[c];
#pragma unroll
    for (int q = 0; q < 8; q++) {
        float4 v = w2[q];
        acc += v.x * sh[4 * q + 0] + v.y * sh[4 * q + 1]
             + v.z * sh[4 * q + 2] + v.w * sh[4 * q + 3];
    }
    const float gate = 1.f / (1.f + expf(-acc));
    d_wt[b * NC + c] = gate * theta_w[c];
    d_wp[b * NC + c] = gate * phi_w[c];
    d_wg[b * NC + c] = gate * g_w[c];

    if (b == 0) {
        const float inv = bn_gamma[c] * rsqrtf(bn_var[c] + BN_EPS);
        d_coefA[c] = W_w[c] * inv;
        d_coefB[c] = (W_b[c] - bn_mean[c]) * inv + bn_beta[c];
    }
}

// ============================================================
// K3: partial projections over a 64-channel chunk (float4 loads).
// grid = (NTILE*CCH, NB) = (72, 16) = 1152 blocks, block = 128.
// REVERSED traversal so it starts on the x tail k_pool left L2-hot.
// ============================================================
__global__ void k_proj(const float* __restrict__ x) {
    const int b     = NB - 1 - blockIdx.y;                    // reversed
    const int xi    = gridDim.x - 1 - blockIdx.x;             // reversed
    const int chunk = xi % CCH;
    const int tile  = xi / CCH;
    __shared__ float swt[CPB], swp[CPB], swg[CPB];
    if (threadIdx.x < CPB) {
        const int ci = b * NC + chunk * CPB + threadIdx.x;
        swt[threadIdx.x] = d_wt[ci];
        swp[threadIdx.x] = d_wp[ci];
        swg[threadIdx.x] = d_wg[ci];
    }
    __syncthreads();

    const int n0 = tile * 512 + threadIdx.x * 4;
    const float* xb = x + ((size_t)b * NC + chunk * CPB) * HN + n0;

    float4 at = make_float4(0.f, 0.f, 0.f, 0.f);
    float4 ap = make_float4(0.f, 0.f, 0.f, 0.f);
    float4 ag = make_float4(0.f, 0.f, 0.f, 0.f);
#pragma unroll 8
    for (int c = 0; c < CPB; c++) {
        const float4 v = *(const float4*)(xb + (size_t)c * HN);
        const float wt = swt[c], wp = swp[c], wg = swg[c];
        at.x = fmaf(v.x, wt, at.x); at.y = fmaf(v.y, wt, at.y);
        at.z = fmaf(v.z, wt, at.z); at.w = fmaf(v.w, wt, at.w);
        ap.x = fmaf(v.x, wp, ap.x); ap.y = fmaf(v.y, wp, ap.y);
        ap.z = fmaf(v.z, wp, ap.z); ap.w = fmaf(v.w, wp, ap.w);
        ag.x = fmaf(v.x, wg, ag.x); ag.y = fmaf(v.y, wg, ag.y);
        ag.z = fmaf(v.z, wg, ag.z); ag.w = fmaf(v.w, wg, ag.w);
    }
    const size_t po = ((size_t)chunk * NB + b) * HN + n0;
    *(float4*)(d_thp + po) = at;
    *(float4*)(d_php + po) = ap;
    *(float4*)(d_ggp + po) = ag;
}

// ============================================================
// K3b: phi*g partial sums ONLY (theta folded into k_out).
// grid = NB*CTILE = 576 blocks, block = 128; one float per thread.
// ============================================================
__global__ void k_comb(const float* __restrict__ phi_b,
                       const float* __restrict__ g_b) {
    const int b    = blockIdx.x / CTILE;
    const int tile = blockIdx.x % CTILE;
    const int n    = tile * 128 + threadIdx.x;

    float ap = phi_b[0];
    float ag = g_b[0];
#pragma unroll
    for (int k = 0; k < CCH; k++) {
        const size_t po = ((size_t)k * NB + b) * HN + n;
        ap += d_php[po];
        ag += d_ggp[po];
    }

    float prod = ap * ag;
#pragma unroll
    for (int off = 16; off; off >>= 1) prod += __shfl_xor_sync(0xffffffffu, prod, off);
    __shared__ float red[4];
    if ((threadIdx.x & 31) == 0) red[threadIdx.x >> 5] = prod;
    __syncthreads();
    if (threadIdx.x == 0)
        d_spart[blockIdx.x] = red[0] + red[1] + red[2] + red[3];
}

// ============================================================
// K4: out = x + th(b,n) * s(b) * coefA(c) + coefB(c)
// grid = (NTILE, OCH, NB) = 2304 blocks, block = 128.
// theta summed from d_thp chunk partials (L2-hot, amortized over
// 32 channel iterations); s(b) warp-parallel from d_spart.
// ============================================================
__global__ void k_out(const float* __restrict__ x, float* __restrict__ out,
                      const float* __restrict__ theta_b) {
    const int b  = blockIdx.z;
    const int c0 = blockIdx.y * OCPB;
    const int n0 = blockIdx.x * 512 + threadIdx.x * 4;

    __shared__ float sS;
    __shared__ float sA[OCPB], sB[OCPB];
    if (threadIdx.x < 32) {                 // warp 0: parallel s reduction
        float s = (threadIdx.x < CTILE) ? d_spart[b * CTILE + threadIdx.x] : 0.f;
        if (threadIdx.x + 32 < CTILE) s += d_spart[b * CTILE + threadIdx.x + 32];
#pragma unroll
        for (int off = 16; off; off >>= 1) s += __shfl_xor_sync(0xffffffffu, s, off);
        if (threadIdx.x == 0) sS = s * (1.0f / HN);
    }
    __syncthreads();
    if (threadIdx.x < OCPB) {
        const int c = c0 + threadIdx.x;
        sA[threadIdx.x] = sS * d_coefA[c];
        sB[threadIdx.x] = d_coefB[c];
    }
    __syncthreads();

    // theta(b, n0..n0+3) = bias + sum of 8 chunk partials (L2-hot)
    const float tb = theta_b[0];
    float4 tv = make_float4(tb, tb, tb, tb);
#pragma unroll
    for (int k = 0; k < CCH; k++) {
        const float4 t = *(const float4*)(d_thp + ((size_t)k * NB + b) * HN + n0);
        tv.x += t.x; tv.y += t.y; tv.z += t.z; tv.w += t.w;
    }

    const float*  xb = x   + ((size_t)b * NC + c0) * HN + n0;
    float*        ob = out + ((size_t)b * NC + c0) * HN + n0;

#pragma unroll 8
    for (int c = 0; c < OCPB; c++) {
        const float4 xv = __ldcs((const float4*)(xb + (size_t)c * HN));
        const float a = sA[c], bb = sB[c];
        float4 o;
        o.x = fmaf(tv.x, a, bb) + xv.x;
        o.y = fmaf(tv.y, a, bb) + xv.y;
        o.z = fmaf(tv.z, a, bb) + xv.z;
        o.w = fmaf(tv.w, a, bb) + xv.w;
        __stcs((float4*)(ob + (size_t)c * HN), o);
    }
}

// ============================================================
extern "C" void kernel_launch(void* const* d_in, const int* in_sizes, int n_in,
                              void* d_out, int out_size) {
    const float* x        = (const float*)d_in[0];
    const float* se_w1    = (const float*)d_in[1];
    const float* se_b1    = (const float*)d_in[2];
    const float* se_w2    = (const float*)d_in[3];
    const float* se_b2    = (const float*)d_in[4];
    const float* g_w      = (const float*)d_in[5];
    const float* g_b      = (const float*)d_in[6];
    const float* theta_w  = (const float*)d_in[7];
    const float* theta_b  = (const float*)d_in[8];
    const float* phi_w    = (const float*)d_in[9];
    const float* phi_b    = (const float*)d_in[10];
    const float* W_w      = (const float*)d_in[11];
    const float* W_b      = (const float*)d_in[12];
    const float* bn_gamma = (const float*)d_in[13];
    const float* bn_beta  = (const float*)d_in[14];
    const float* bn_mean  = (const float*)d_in[15];
    const float* bn_var   = (const float*)d_in[16];
    float* out = (float*)d_out;

    k_pool<<<NB * NC / 8, 256>>>(x);
    k_se<<<NB, 512>>>(se_w1, se_b1, se_w2, se_b2, g_w, theta_w, phi_w,
                      W_w, W_b, bn_gamma, bn_beta, bn_mean, bn_var);
    k_proj<<<dim3(NTILE * CCH, NB), 128>>>(x);
    k_comb<<<NB * CTILE, 128>>>(phi_b, g_b);
    k_out<<<dim3(NTILE, OCH, NB), 128>>>(x, out, theta_b);
}

// round 15
// speedup vs baseline: 1.0996x; 1.0996x over previous
#include <cuda_runtime.h>

#define NB   16
#define NC   512
#define HN   4608      // H*W = 96*48
#define SEC  32        // SE bottleneck
#define NTILE 9        // n-tiles of 512 floats
#define CCH  8         // C chunks in k_proj
#define CPB  (NC/CCH)  // 64 channels per proj block
#define OCH  16        // C chunks in k_out
#define OCPB (NC/OCH)  // 32 channels per out block
#define BN_EPS 1e-5f

// ---- scratch (device globals; no allocations allowed) ----
__device__ float d_xp[NB * NC];          // channel means
__device__ float d_wt[NB * NC];          // gate * theta_w
__device__ float d_wp[NB * NC];          // gate * phi_w
__device__ float d_wg[NB * NC];          // gate * g_w
__device__ float d_thp[CCH * NB * HN];   // theta partials per C-chunk
__device__ float d_php[CCH * NB * HN];   // phi partials
__device__ float d_ggp[CCH * NB * HN];   // g partials
__device__ float d_th[NB * HN];          // final theta projection (incl. bias)
__device__ float d_spart[NB * NTILE];    // per-(b,tile) partial of sum(phi*g)
__device__ float d_coefA[NC];            // W_w * gamma/sqrt(var+eps)
__device__ float d_coefB[NC];            // (W_b-mean)*inv + beta
__device__ int   d_cnt[NB * NTILE];      // chunk-completion counters (zeroed each launch by k_se)

// ============================================================
// K1: per-(b,c) spatial mean. Warp-per-row: grid = NB*NC/8,
// block = 256 (8 warps). FORWARD order; default cache policy so
// the tail of x stays L2-resident for k_proj (which reads reversed).
// ============================================================
__global__ void k_pool(const float* __restrict__ x) {
    const int warp = threadIdx.x >> 5, lane = threadIdx.x & 31;
    const int row  = blockIdx.x * 8 + warp;          // b*NC + c
    const float4* xr = (const float4*)(x + (size_t)row * HN);
    float s = 0.f;
#pragma unroll
    for (int i = 0; i < 36; i++) {                   // HN/4/32 = 36
        float4 v = xr[lane + i * 32];
        s += (v.x + v.y) + (v.z + v.w);
    }
#pragma unroll
    for (int off = 16; off; off >>= 1) s += __shfl_xor_sync(0xffffffffu, s, off);
    if (lane == 0) d_xp[row] = s * (1.0f / HN);
}

// ============================================================
// K2: full SE MLP + fused weights + BN coefs + counter reset.
// grid = NB, block = 512.
// ============================================================
__global__ void k_se(const float* __restrict__ se_w1,
                     const float* __restrict__ se_b1,
                     const float* __restrict__ se_w2,
                     const float* __restrict__ se_b2,
                     const float* __restrict__ g_w,
                     const float* __restrict__ theta_w,
                     const float* __restrict__ phi_w,
                     const float* __restrict__ W_w,
                     const float* __restrict__ W_b,
                     const float* __restrict__ bn_gamma,
                     const float* __restrict__ bn_beta,
                     const float* __restrict__ bn_mean,
                     const float* __restrict__ bn_var) {
    const int b    = blockIdx.x;
    const int c    = threadIdx.x;
    const int lane = c & 31, warp = c >> 5;          // 16 warps

    // reset this batch's chunk counters for k_proj's fused combine
    if (c < NTILE) d_cnt[b * NTILE + c] = 0;

    __shared__ float sh[SEC];
    // stage 1: hid = relu(xp @ W1^T + b1); 16 warps x 2 outputs each
#pragma unroll
    for (int j = warp; j < SEC; j += 16) {
        float acc = 0.f;
#pragma unroll
        for (int k = 0; k < 16; k++) {
            const int cc = k * 32 + lane;
            acc += d_xp[b * NC + cc] * se_w1[j * NC + cc];
        }
#pragma unroll
        for (int off = 16; off; off >>= 1) acc += __shfl_xor_sync(0xffffffffu, acc, off);
        if (lane == 0) sh[j] = fmaxf(acc + se_b1[j], 0.f);
    }
    __syncthreads();

    // stage 2: gate = sigmoid(hid @ W2^T + b2), fused per-channel weights
    const float4* w2 = (const float4*)(se_w2 + c * SEC);
    float acc = se_b2[c];
#pragma unroll
    for (int q = 0; q < 8; q++) {
        float4 v = w2[q];
        acc += v.x * sh[4 * q + 0] + v.y * sh[4 * q + 1]
             + v.z * sh[4 * q + 2] + v.w * sh[4 * q + 3];
    }
    const float gate = 1.f / (1.f + expf(-acc));
    d_wt[b * NC + c] = gate * theta_w[c];
    d_wp[b * NC + c] = gate * phi_w[c];
    d_wg[b * NC + c] = gate * g_w[c];

    if (b == 0) {
        const float inv = bn_gamma[c] * rsqrtf(bn_var[c] + BN_EPS);
        d_coefA[c] = W_w[c] * inv;
        d_coefB[c] = (W_b[c] - bn_mean[c]) * inv + bn_beta[c];
    }
}

// ============================================================
// K3: partial projections over a 64-channel chunk (float4 loads),
// with FUSED combine: the last of the 8 chunk-blocks per (b,tile)
// sums the (L2-hot) partials into d_th and d_spart.
// grid = (NTILE*CCH, NB) = (72, 16) = 1152 blocks, block = 128.
// REVERSED traversal so it starts on the x tail k_pool left L2-hot.
// ============================================================
__global__ void k_proj(const float* __restrict__ x,
                       const float* __restrict__ theta_b,
                       const float* __restrict__ phi_b,
                       const float* __restrict__ g_b) {
    const int b     = NB - 1 - blockIdx.y;                    // reversed
    const int xi    = gridDim.x - 1 - blockIdx.x;             // reversed
    const int chunk = xi % CCH;
    const int tile  = xi / CCH;
    __shared__ float swt[CPB], swp[CPB], swg[CPB];
    if (threadIdx.x < CPB) {
        const int ci = b * NC + chunk * CPB + threadIdx.x;
        swt[threadIdx.x] = d_wt[ci];
        swp[threadIdx.x] = d_wp[ci];
        swg[threadIdx.x] = d_wg[ci];
    }
    __syncthreads();

    const int n0 = tile * 512 + threadIdx.x * 4;
    const float* xb = x + ((size_t)b * NC + chunk * CPB) * HN + n0;

    float4 at = make_float4(0.f, 0.f, 0.f, 0.f);
    float4 ap = make_float4(0.f, 0.f, 0.f, 0.f);
    float4 ag = make_float4(0.f, 0.f, 0.f, 0.f);
#pragma unroll 8
    for (int c = 0; c < CPB; c++) {
        const float4 v = *(const float4*)(xb + (size_t)c * HN);
        const float wt = swt[c], wp = swp[c], wg = swg[c];
        at.x = fmaf(v.x, wt, at.x); at.y = fmaf(v.y, wt, at.y);
        at.z = fmaf(v.z, wt, at.z); at.w = fmaf(v.w, wt, at.w);
        ap.x = fmaf(v.x, wp, ap.x); ap.y = fmaf(v.y, wp, ap.y);
        ap.z = fmaf(v.z, wp, ap.z); ap.w = fmaf(v.w, wp, ap.w);
        ag.x = fmaf(v.x, wg, ag.x); ag.y = fmaf(v.y, wg, ag.y);
        ag.z = fmaf(v.z, wg, ag.z); ag.w = fmaf(v.w, wg, ag.w);
    }
    const size_t po = ((size_t)chunk * NB + b) * HN + n0;
    *(float4*)(d_thp + po) = at;
    *(float4*)(d_php + po) = ap;
    *(float4*)(d_ggp + po) = ag;

    // ---- fused combine: last block of this (b,tile) group does it ----
    __threadfence();                         // make this block's partials visible
    __shared__ int s_last;
    __syncthreads();                         // all threads past their fence
    if (threadIdx.x == 0)
        s_last = (atomicAdd(&d_cnt[b * NTILE + tile], 1) == CCH - 1);
    __syncthreads();
    if (!s_last) return;

    // combine 8 chunk partials for this 512-n range (all L2-hot)
    float4 ct = make_float4(theta_b[0], theta_b[0], theta_b[0], theta_b[0]);
    float4 cp = make_float4(phi_b[0], phi_b[0], phi_b[0], phi_b[0]);
    float4 cg = make_float4(g_b[0], g_b[0], g_b[0], g_b[0]);
#pragma unroll
    for (int k = 0; k < CCH; k++) {
        const size_t q = ((size_t)k * NB + b) * HN + n0;
        const float4 t = *(const float4*)(d_thp + q);
        const float4 p = *(const float4*)(d_php + q);
        const float4 g = *(const float4*)(d_ggp + q);
        ct.x += t.x; ct.y += t.y; ct.z += t.z; ct.w += t.w;
        cp.x += p.x; cp.y += p.y; cp.z += p.z; cp.w += p.w;
        cg.x += g.x; cg.y += g.y; cg.z += g.z; cg.w += g.w;
    }
    *(float4*)(d_th + b * HN + n0) = ct;

    float prod = cp.x * cg.x + cp.y * cg.y + cp.z * cg.z + cp.w * cg.w;
#pragma unroll
    for (int off = 16; off; off >>= 1) prod += __shfl_xor_sync(0xffffffffu, prod, off);
    __shared__ float red[4];
    if ((threadIdx.x & 31) == 0) red[threadIdx.x >> 5] = prod;
    __syncthreads();
    if (threadIdx.x == 0)
        d_spart[b * NTILE + tile] = red[0] + red[1] + red[2] + red[3];
}

// ============================================================
// K4: out = x + th(b,n) * s(b) * coefA(c) + coefB(c)
// grid = (NTILE, OCH, NB) = 2304 blocks, block = 128.
// s(b) warp-parallel reduced from d_spart (9 entries, L2-hot).
// ============================================================
__global__ void k_out(const float* __restrict__ x, float* __restrict__ out) {
    const int b  = blockIdx.z;
    const int c0 = blockIdx.y * OCPB;
    const int n0 = blockIdx.x * 512 + threadIdx.x * 4;

    __shared__ float sS;
    __shared__ float sA[OCPB], sB[OCPB];
    if (threadIdx.x < 32) {                 // warp 0: parallel s reduction
        float s = (threadIdx.x < NTILE) ? d_spart[b * NTILE + threadIdx.x] : 0.f;
#pragma unroll
        for (int off = 16; off; off >>= 1) s += __shfl_xor_sync(0xffffffffu, s, off);
        if (threadIdx.x == 0) sS = s * (1.0f / HN);
    }
    __syncthreads();
    if (threadIdx.x < OCPB) {
        const int c = c0 + threadIdx.x;
        sA[threadIdx.x] = sS * d_coefA[c];
        sB[threadIdx.x] = d_coefB[c];
    }
    __syncthreads();

    const float4 tv = *(const float4*)(d_th + b * HN + n0);
    const float*  xb = x   + ((size_t)b * NC + c0) * HN + n0;
    float*        ob = out + ((size_t)b * NC + c0) * HN + n0;

#pragma unroll 8
    for (int c = 0; c < OCPB; c++) {
        const float4 xv = __ldcs((const float4*)(xb + (size_t)c * HN));
        const float a = sA[c], bb = sB[c];
        float4 o;
        o.x = fmaf(tv.x, a, bb) + xv.x;
        o.y = fmaf(tv.y, a, bb) + xv.y;
        o.z = fmaf(tv.z, a, bb) + xv.z;
        o.w = fmaf(tv.w, a, bb) + xv.w;
        __stcs((float4*)(ob + (size_t)c * HN), o);
    }
}

// ============================================================
extern "C" void kernel_launch(void* const* d_in, const int* in_sizes, int n_in,
                              void* d_out, int out_size) {
    const float* x        = (const float*)d_in[0];
    const float* se_w1    = (const float*)d_in[1];
    const float* se_b1    = (const float*)d_in[2];
    const float* se_w2    = (const float*)d_in[3];
    const float* se_b2    = (const float*)d_in[4];
    const float* g_w      = (const float*)d_in[5];
    const float* g_b      = (const float*)d_in[6];
    const float* theta_w  = (const float*)d_in[7];
    const float* theta_b  = (const float*)d_in[8];
    const float* phi_w    = (const float*)d_in[9];
    const float* phi_b    = (const float*)d_in[10];
    const float* W_w      = (const float*)d_in[11];
    const float* W_b      = (const float*)d_in[12];
    const float* bn_gamma = (const float*)d_in[13];
    const float* bn_beta  = (const float*)d_in[14];
    const float* bn_mean  = (const float*)d_in[15];
    const float* bn_var   = (const float*)d_in[16];
    float* out = (float*)d_out;

    k_pool<<<NB * NC / 8, 256>>>(x);
    k_se<<<NB, 512>>>(se_w1, se_b1, se_w2, se_b2, g_w, theta_w, phi_w,
                      W_w, W_b, bn_gamma, bn_beta, bn_mean, bn_var);
    k_proj<<<dim3(NTILE * CCH, NB), 128>>>(x, theta_b, phi_b, g_b);
    k_out<<<dim3(NTILE, OCH, NB), 128>>>(x, out);
}

// round 16
// speedup vs baseline: 1.1096x; 1.0091x over previous
#include <cuda_runtime.h>

#define NB   16
#define NC   512
#define HN   4608      // H*W = 96*48
#define SEC  32        // SE bottleneck
#define NTILE 9        // n-tiles of 512 floats
#define CCH  8         // C chunks in k_proj
#define CPB  (NC/CCH)  // 64 channels per proj block
#define OCH  16        // C chunks in k_out
#define OCPB (NC/OCH)  // 32 channels per out block
#define PBLK 64        // pool blocks per batch (NC/8)
#define BN_EPS 1e-5f

// ---- scratch (device globals; no allocations allowed) ----
__device__ float d_xp[NB * NC];          // channel means
__device__ float d_wt[NB * NC];          // gate * theta_w
__device__ float d_wp[NB * NC];          // gate * phi_w
__device__ float d_wg[NB * NC];          // gate * g_w
__device__ float d_thp[CCH * NB * HN];   // theta partials per C-chunk
__device__ float d_php[CCH * NB * HN];   // phi partials
__device__ float d_ggp[CCH * NB * HN];   // g partials
__device__ float d_th[NB * HN];          // final theta projection (incl. bias)
__device__ float d_spart[NB * NTILE];    // per-(b,tile) partial of sum(phi*g)
__device__ float d_coefA[NC];            // W_w * gamma/sqrt(var+eps)
__device__ float d_coefB[NC];            // (W_b-mean)*inv + beta
__device__ int   d_pcnt[NB];             // pool completion counters (self-resetting)
__device__ int   d_cnt[NB * NTILE];      // proj chunk counters (self-resetting)

// ============================================================
// K1: per-(b,c) spatial mean (warp-per-row, 8 rows/block) WITH
// fused SE tail: the last of the 64 blocks per batch runs the
// SE MLP + fused-weight emit for that b. Counters self-reset.
// grid = NB*PBLK = 1024 blocks, block = 256.
// ============================================================
__global__ void k_pool(const float* __restrict__ x,
                       const float* __restrict__ se_w1,
                       const float* __restrict__ se_b1,
                       const float* __restrict__ se_w2,
                       const float* __restrict__ se_b2,
                       const float* __restrict__ g_w,
                       const float* __restrict__ theta_w,
                       const float* __restrict__ phi_w,
                       const float* __restrict__ W_w,
                       const float* __restrict__ W_b,
                       const float* __restrict__ bn_gamma,
                       const float* __restrict__ bn_beta,
                       const float* __restrict__ bn_mean,
                       const float* __restrict__ bn_var) {
    const int warp = threadIdx.x >> 5, lane = threadIdx.x & 31;
    const int row  = blockIdx.x * 8 + warp;          // b*NC + c
    const int b    = blockIdx.x / PBLK;
    {
        const float4* xr = (const float4*)(x + (size_t)row * HN);
        float s = 0.f;
#pragma unroll
        for (int i = 0; i < 36; i++) {               // HN/4/32 = 36
            float4 v = xr[lane + i * 32];
            s += (v.x + v.y) + (v.z + v.w);
        }
#pragma unroll
        for (int off = 16; off; off >>= 1) s += __shfl_xor_sync(0xffffffffu, s, off);
        if (lane == 0) d_xp[row] = s * (1.0f / HN);
    }

    // ---- last-block election for this batch ----
    __threadfence();
    __syncthreads();
    __shared__ int s_last;
    if (threadIdx.x == 0) {
        const int t = atomicAdd(&d_pcnt[b], 1);
        s_last = (t == PBLK - 1);
        if (s_last) atomicExch(&d_pcnt[b], 0);       // self-reset for next replay
    }
    __syncthreads();
    if (!s_last) return;
    __threadfence();                                  // acquire: see all d_xp rows

    // ---- SE MLP for batch b (256 threads) ----
    __shared__ float sh[SEC];
    // stage 1: hid = relu(xp @ W1^T + b1); 8 warps x 4 outputs each
#pragma unroll
    for (int j = warp; j < SEC; j += 8) {
        float acc = 0.f;
#pragma unroll
        for (int k = 0; k < 16; k++) {
            const int cc = k * 32 + lane;
            acc += d_xp[b * NC + cc] * se_w1[j * NC + cc];
        }
#pragma unroll
        for (int off = 16; off; off >>= 1) acc += __shfl_xor_sync(0xffffffffu, acc, off);
        if (lane == 0) sh[j] = fmaxf(acc + se_b1[j], 0.f);
    }
    __syncthreads();

    // stage 2: gate = sigmoid(hid @ W2^T + b2); 2 channels per thread
    for (int c = threadIdx.x; c < NC; c += 256) {
        const float4* w2 = (const float4*)(se_w2 + c * SEC);
        float acc = se_b2[c];
#pragma unroll
        for (int q = 0; q < 8; q++) {
            float4 v = w2[q];
            acc += v.x * sh[4 * q + 0] + v.y * sh[4 * q + 1]
                 + v.z * sh[4 * q + 2] + v.w * sh[4 * q + 3];
        }
        const float gate = 1.f / (1.f + expf(-acc));
        d_wt[b * NC + c] = gate * theta_w[c];
        d_wp[b * NC + c] = gate * phi_w[c];
        d_wg[b * NC + c] = gate * g_w[c];

        if (b == 0) {
            const float inv = bn_gamma[c] * rsqrtf(bn_var[c] + BN_EPS);
            d_coefA[c] = W_w[c] * inv;
            d_coefB[c] = (W_b[c] - bn_mean[c]) * inv + bn_beta[c];
        }
    }
}

// ============================================================
// K3: partial projections over a 64-channel chunk (float4 loads),
// with FUSED combine: the last of the 8 chunk-blocks per (b,tile)
// sums the (L2-hot) partials into d_th and d_spart. Counters
// self-reset. grid = (NTILE*CCH, NB) = 1152 blocks, block = 128.
// REVERSED traversal so it starts on the x tail k_pool left L2-hot.
// ============================================================
__global__ void k_proj(const float* __restrict__ x,
                       const float* __restrict__ theta_b,
                       const float* __restrict__ phi_b,
                       const float* __restrict__ g_b) {
    const int b     = NB - 1 - blockIdx.y;                    // reversed
    const int xi    = gridDim.x - 1 - blockIdx.x;             // reversed
    const int chunk = xi % CCH;
    const int tile  = xi / CCH;
    __shared__ float swt[CPB], swp[CPB], swg[CPB];
    if (threadIdx.x < CPB) {
        const int ci = b * NC + chunk * CPB + threadIdx.x;
        swt[threadIdx.x] = d_wt[ci];
        swp[threadIdx.x] = d_wp[ci];
        swg[threadIdx.x] = d_wg[ci];
    }
    __syncthreads();

    const int n0 = tile * 512 + threadIdx.x * 4;
    const float* xb = x + ((size_t)b * NC + chunk * CPB) * HN + n0;

    float4 at = make_float4(0.f, 0.f, 0.f, 0.f);
    float4 ap = make_float4(0.f, 0.f, 0.f, 0.f);
    float4 ag = make_float4(0.f, 0.f, 0.f, 0.f);
#pragma unroll 8
    for (int c = 0; c < CPB; c++) {
        const float4 v = *(const float4*)(xb + (size_t)c * HN);
        const float wt = swt[c], wp = swp[c], wg = swg[c];
        at.x = fmaf(v.x, wt, at.x); at.y = fmaf(v.y, wt, at.y);
        at.z = fmaf(v.z, wt, at.z); at.w = fmaf(v.w, wt, at.w);
        ap.x = fmaf(v.x, wp, ap.x); ap.y = fmaf(v.y, wp, ap.y);
        ap.z = fmaf(v.z, wp, ap.z); ap.w = fmaf(v.w, wp, ap.w);
        ag.x = fmaf(v.x, wg, ag.x); ag.y = fmaf(v.y, wg, ag.y);
        ag.z = fmaf(v.z, wg, ag.z); ag.w = fmaf(v.w, wg, ag.w);
    }
    const size_t po = ((size_t)chunk * NB + b) * HN + n0;
    *(float4*)(d_thp + po) = at;
    *(float4*)(d_php + po) = ap;
    *(float4*)(d_ggp + po) = ag;

    // ---- fused combine: last block of this (b,tile) group does it ----
    __threadfence();                         // make this block's partials visible
    __shared__ int s_last;
    __syncthreads();
    if (threadIdx.x == 0) {
        const int t = atomicAdd(&d_cnt[b * NTILE + tile], 1);
        s_last = (t == CCH - 1);
        if (s_last) atomicExch(&d_cnt[b * NTILE + tile], 0);  // self-reset
    }
    __syncthreads();
    if (!s_last) return;
    __threadfence();                         // acquire: see all chunk partials

    float4 ct = make_float4(theta_b[0], theta_b[0], theta_b[0], theta_b[0]);
    float4 cp = make_float4(phi_b[0], phi_b[0], phi_b[0], phi_b[0]);
    float4 cg = make_float4(g_b[0], g_b[0], g_b[0], g_b[0]);
#pragma unroll
    for (int k = 0; k < CCH; k++) {
        const size_t q = ((size_t)k * NB + b) * HN + n0;
        const float4 t = *(const float4*)(d_thp + q);
        const float4 p = *(const float4*)(d_php + q);
        const float4 g = *(const float4*)(d_ggp + q);
        ct.x += t.x; ct.y += t.y; ct.z += t.z; ct.w += t.w;
        cp.x += p.x; cp.y += p.y; cp.z += p.z; cp.w += p.w;
        cg.x += g.x; cg.y += g.y; cg.z += g.z; cg.w += g.w;
    }
    *(float4*)(d_th + b * HN + n0) = ct;

    float prod = cp.x * cg.x + cp.y * cg.y + cp.z * cg.z + cp.w * cg.w;
#pragma unroll
    for (int off = 16; off; off >>= 1) prod += __shfl_xor_sync(0xffffffffu, prod, off);
    __shared__ float red[4];
    if ((threadIdx.x & 31) == 0) red[threadIdx.x >> 5] = prod;
    __syncthreads();
    if (threadIdx.x == 0)
        d_spart[b * NTILE + tile] = red[0] + red[1] + red[2] + red[3];
}

// ============================================================
// K4: out = x + th(b,n) * s(b) * coefA(c) + coefB(c)
// grid = (NTILE, OCH, NB) = 2304 blocks, block = 128.
// s(b) warp-parallel reduced from d_spart (9 entries, L2-hot).
// ============================================================
__global__ void k_out(const float* __restrict__ x, float* __restrict__ out) {
    const int b  = blockIdx.z;
    const int c0 = blockIdx.y * OCPB;
    const int n0 = blockIdx.x * 512 + threadIdx.x * 4;

    __shared__ float sS;
    __shared__ float sA[OCPB], sB[OCPB];
    if (threadIdx.x < 32) {                 // warp 0: parallel s reduction
        float s = (threadIdx.x < NTILE) ? d_spart[b * NTILE + threadIdx.x] : 0.f;
#pragma unroll
        for (int off = 16; off; off >>= 1) s += __shfl_xor_sync(0xffffffffu, s, off);
        if (threadIdx.x == 0) sS = s * (1.0f / HN);
    }
    __syncthreads();
    if (threadIdx.x < OCPB) {
        const int c = c0 + threadIdx.x;
        sA[threadIdx.x] = sS * d_coefA[c];
        sB[threadIdx.x] = d_coefB[c];
    }
    __syncthreads();

    const float4 tv = *(const float4*)(d_th + b * HN + n0);
    const float*  xb = x   + ((size_t)b * NC + c0) * HN + n0;
    float*        ob = out + ((size_t)b * NC + c0) * HN + n0;

#pragma unroll 8
    for (int c = 0; c < OCPB; c++) {
        const float4 xv = __ldcs((const float4*)(xb + (size_t)c * HN));
        const float a = sA[c], bb = sB[c];
        float4 o;
        o.x = fmaf(tv.x, a, bb) + xv.x;
        o.y = fmaf(tv.y, a, bb) + xv.y;
        o.z = fmaf(tv.z, a, bb) + xv.z;
        o.w = fmaf(tv.w, a, bb) + xv.w;
        __stcs((float4*)(ob + (size_t)c * HN), o);
    }
}

// ============================================================
extern "C" void kernel_launch(void* const* d_in, const int* in_sizes, int n_in,
                              void* d_out, int out_size) {
    const float* x        = (const float*)d_in[0];
    const float* se_w1    = (const float*)d_in[1];
    const float* se_b1    = (const float*)d_in[2];
    const float* se_w2    = (const float*)d_in[3];
    const float* se_b2    = (const float*)d_in[4];
    const float* g_w      = (const float*)d_in[5];
    const float* g_b      = (const float*)d_in[6];
    const float* theta_w  = (const float*)d_in[7];
    const float* theta_b  = (const float*)d_in[8];
    const float* phi_w    = (const float*)d_in[9];
    const float* phi_b    = (const float*)d_in[10];
    const float* W_w      = (const float*)d_in[11];
    const float* W_b      = (const float*)d_in[12];
    const float* bn_gamma = (const float*)d_in[13];
    const float* bn_beta  = (const float*)d_in[14];
    const float* bn_mean  = (const float*)d_in[15];
    const float* bn_var   = (const float*)d_in[16];
    float* out = (float*)d_out;

    k_pool<<<NB * PBLK, 256>>>(x, se_w1, se_b1, se_w2, se_b2, g_w, theta_w,
                               phi_w, W_w, W_b, bn_gamma, bn_beta, bn_mean, bn_var);
    k_proj<<<dim3(NTILE * CCH, NB), 128>>>(x, theta_b, phi_b, g_b);
    k_out<<<dim3(NTILE, OCH, NB), 128>>>(x, out);
}